// round 5
// baseline (speedup 1.0000x reference)
#include <cuda_runtime.h>
#include <cuda_fp16.h>
#include <cstdint>

// Problem dims
#define M_TOTAL 16384   // 8 * 2048
#define N_TOTAL 4096
#define K_TOTAL 4096

// GEMM tiling: 128x128 CTA tile, 2 CTAs resident per SM
#define BM 128
#define BN 128
#define BK 64
#define NK (K_TOTAL / BK)        // 64 mainloop iterations
#define STAGES 3
#define THREADS 256              // 8 warps; 2x4 warp grid; warp tile 64x32

#define A_TILE_BYTES (BM * BK * 2)   // 16384
#define B_TILE_BYTES (BN * BK * 2)   // 16384
#define STAGE_BYTES (A_TILE_BYTES + B_TILE_BYTES)  // 32768
#define SMEM_BIAS   0                // 128 floats = 512 B
#define SMEM_STAGE0 1024
#define SMEM_TOTAL  (SMEM_STAGE0 + STAGES * STAGE_BYTES)  // 99328 (x2 CTAs <= 227KB)

// fp16 operand buffers (device globals: no runtime allocation allowed)
__device__ __align__(1024) __half g_xh[(size_t)M_TOTAL * K_TOTAL];
__device__ __align__(1024) __half g_wh[(size_t)N_TOTAL * K_TOTAL];

// ---------------------------------------------------------------- helpers

__device__ __forceinline__ uint32_t smem_u32(const void* p) {
    uint32_t a;
    asm("{ .reg .u64 t; cvta.to.shared.u64 t, %1; cvt.u32.u64 %0, t; }" : "=r"(a) : "l"(p));
    return a;
}

__device__ __forceinline__ uint32_t swz128(uint32_t off) {
    return off ^ ((off >> 3) & 0x70);
}

__device__ __forceinline__ float quantize_ste(float w) {
    float a = fminf(fabsf(w), 1.0f);
    float q = rintf(a * 255.0f) * (1.0f / 255.0f);
    return copysignf(q, w);
}

__device__ __forceinline__ uint32_t h2_as_u32(__half2 h) {
    return *reinterpret_cast<uint32_t*>(&h);
}

__device__ __forceinline__ void cp_async16(uint32_t dst, const void* src) {
    asm volatile("cp.async.cg.shared.global [%0], [%1], 16;" :: "r"(dst), "l"(src) : "memory");
}
#define CP_COMMIT() asm volatile("cp.async.commit_group;" ::: "memory")
#define CP_WAIT(n)  asm volatile("cp.async.wait_group %0;" :: "n"(n) : "memory")

__device__ __forceinline__ void ldsm_x4(uint32_t* r, uint32_t addr) {
    asm volatile("ldmatrix.sync.aligned.m8n8.x4.shared.b16 {%0,%1,%2,%3}, [%4];"
                 : "=r"(r[0]), "=r"(r[1]), "=r"(r[2]), "=r"(r[3]) : "r"(addr));
}

__device__ __forceinline__ void mma_16816(float* c, const uint32_t* a, uint32_t b0, uint32_t b1) {
    asm volatile(
        "mma.sync.aligned.m16n8k16.row.col.f32.f16.f16.f32 "
        "{%0,%1,%2,%3}, {%4,%5,%6,%7}, {%8,%9}, {%0,%1,%2,%3};"
        : "+f"(c[0]), "+f"(c[1]), "+f"(c[2]), "+f"(c[3])
        : "r"(a[0]), "r"(a[1]), "r"(a[2]), "r"(a[3]), "r"(b0), "r"(b1));
}

// ---------------------------------------------------------------- pre-pass kernels

__global__ void convert_x_kernel(const float* __restrict__ x) {
    size_t e = ((size_t)blockIdx.x * blockDim.x + threadIdx.x) * 8;
    float4 a = *reinterpret_cast<const float4*>(x + e);
    float4 b = *reinterpret_cast<const float4*>(x + e + 4);
    uint4 o;
    o.x = h2_as_u32(__floats2half2_rn(a.x, a.y));
    o.y = h2_as_u32(__floats2half2_rn(a.z, a.w));
    o.z = h2_as_u32(__floats2half2_rn(b.x, b.y));
    o.w = h2_as_u32(__floats2half2_rn(b.z, b.w));
    *reinterpret_cast<uint4*>(g_xh + e) = o;
}

__global__ void convert_w_kernel(const float* __restrict__ w) {
    size_t e = ((size_t)blockIdx.x * blockDim.x + threadIdx.x) * 8;
    float4 a = *reinterpret_cast<const float4*>(w + e);
    float4 b = *reinterpret_cast<const float4*>(w + e + 4);
    uint4 o;
    o.x = h2_as_u32(__floats2half2_rn(quantize_ste(a.x), quantize_ste(a.y)));
    o.y = h2_as_u32(__floats2half2_rn(quantize_ste(a.z), quantize_ste(a.w)));
    o.z = h2_as_u32(__floats2half2_rn(quantize_ste(b.x), quantize_ste(b.y)));
    o.w = h2_as_u32(__floats2half2_rn(quantize_ste(b.z), quantize_ste(b.w)));
    *reinterpret_cast<uint4*>(g_wh + e) = o;
}

// no-op: shifts launch index so ncu (-s 5 -c 1) lands on the GEMM
__global__ void align_nop_kernel() {}

// ---------------------------------------------------------------- GEMM kernel
// CTA 128x128, BK=64, 256 threads, 8 warps (2 x 4), warp tile 64x32.
// 2 CTAs/SM; fragments software-pipelined (A ring-3, B double-buffered).

__global__ void __launch_bounds__(THREADS, 2)
bitlinear_gemm(const float* __restrict__ bias, float* __restrict__ out) {
    extern __shared__ char smem[];
    uint32_t sb = smem_u32(smem);
    const int tid = threadIdx.x;
    const int wid = tid >> 5, lane = tid & 31;
    const int warp_m = wid >> 2, warp_n = wid & 3;     // 2 x 4 warps
    const uint32_t mt = blockIdx.y, nt = blockIdx.x;

    float* qb = reinterpret_cast<float*>(smem + SMEM_BIAS);
    if (tid < BN) qb[tid] = quantize_ste(bias[nt * BN + tid]);

    const __half* asrc = g_xh + (size_t)mt * BM * K_TOTAL;
    const __half* bsrc = g_wh + (size_t)nt * BN * K_TOTAL;

    auto load_stage = [&](int s, int kt) {
        uint32_t abase = sb + SMEM_STAGE0 + s * STAGE_BYTES;
        uint32_t bbase = abase + A_TILE_BYTES;
        #pragma unroll
        for (int i = 0; i < 4; i++) {
            int c = tid + i * THREADS;            // 0..1023
            int row = c >> 3, kc = c & 7;
            cp_async16(abase + swz128(row * 128 + kc * 16),
                       asrc + (size_t)row * K_TOTAL + kt * BK + kc * 8);
        }
        #pragma unroll
        for (int i = 0; i < 4; i++) {
            int c = tid + i * THREADS;
            int row = c >> 3, kc = c & 7;
            cp_async16(bbase + swz128(row * 128 + kc * 16),
                       bsrc + (size_t)row * K_TOTAL + kt * BK + kc * 8);
        }
        CP_COMMIT();
    };

    load_stage(0, 0);
    load_stage(1, 1);

    // per-lane ldmatrix row mapping
    const int lrow = (lane & 7) + ((lane >> 3) & 1) * 8;
    const int lhi = lane >> 4;

    float acc[4][4][4];
    #pragma unroll
    for (int i = 0; i < 4; i++)
        #pragma unroll
        for (int j = 0; j < 4; j++)
            #pragma unroll
            for (int c = 0; c < 4; c++) acc[i][j][c] = 0.0f;

    // pipelined fragments: A ring of 3 (one per (kk,mi) step), B 2 buffers (per kk)
    uint32_t A[3][4];        // 12 regs
    uint32_t Bf[2][2][4];    // 16 regs

    for (int kt = 0; kt < NK; kt++) {
        CP_WAIT(1);
        __syncthreads();
        if (kt + 2 < NK) load_stage((kt + 2) % STAGES, kt + 2);

        int s = kt % STAGES;
        uint32_t abase = sb + SMEM_STAGE0 + s * STAGE_BYTES;
        uint32_t bbase = abase + A_TILE_BYTES;

        // A-frag address for linear step t (kk = t>>2, mi = t&3)
        auto a_addr = [&](int t) {
            int kk = t >> 2, mi = t & 3;
            int row = warp_m * 64 + mi * 16 + lrow;
            return abase + swz128(row * 128 + (kk * 2 + lhi) * 16);
        };
        auto load_b = [&](int buf, int kk) {
            #pragma unroll
            for (int ni = 0; ni < 2; ni++) {
                int row = warp_n * 32 + ni * 16 + lrow;
                ldsm_x4(Bf[buf][ni], bbase + swz128(row * 128 + (kk * 2 + lhi) * 16));
            }
        };

        // prologue for this stage
        load_b(0, 0);
        ldsm_x4(A[0], a_addr(0));
        ldsm_x4(A[1], a_addr(1));

        #pragma unroll
        for (int kk = 0; kk < 4; kk++) {
            if (kk < 3) load_b((kk + 1) & 1, kk + 1);      // B for next kk, ~16 MMAs ahead
            #pragma unroll
            for (int mi = 0; mi < 4; mi++) {
                int t = kk * 4 + mi;
                if (t + 2 < 16) ldsm_x4(A[(t + 2) % 3], a_addr(t + 2));  // 8 MMAs ahead
                const uint32_t* af = A[t % 3];
                #pragma unroll
                for (int j = 0; j < 4; j++) {
                    int ni = j >> 1, sel = j & 1;
                    mma_16816(acc[mi][j], af, Bf[kk & 1][ni][0 + sel], Bf[kk & 1][ni][2 + sel]);
                }
            }
        }
    }

    // ---- epilogue: registers -> gmem with quantized bias ----
    const int qrow = lane >> 2, qcol = (lane & 3) * 2;
    #pragma unroll
    for (int mi = 0; mi < 4; mi++) {
        #pragma unroll
        for (int j = 0; j < 4; j++) {
            int n_off = warp_n * 32 + j * 8 + qcol;
            float b0 = qb[n_off], b1 = qb[n_off + 1];
            size_t m0 = (size_t)mt * BM + warp_m * 64 + mi * 16 + qrow;
            float* p0 = out + m0 * N_TOTAL + nt * BN + n_off;
            float* p1 = p0 + 8 * N_TOTAL;
            float2 v0 = {acc[mi][j][0] + b0, acc[mi][j][1] + b1};
            float2 v1 = {acc[mi][j][2] + b0, acc[mi][j][3] + b1};
            *reinterpret_cast<float2*>(p0) = v0;
            *reinterpret_cast<float2*>(p1) = v1;
        }
    }
}

// ---------------------------------------------------------------- launch

extern "C" void kernel_launch(void* const* d_in, const int* in_sizes, int n_in,
                              void* d_out, int out_size) {
    const float* x = (const float*)d_in[0];       // [8, 2048, 4096]
    const float* w = (const float*)d_in[1];       // [4096, 4096]
    const float* b = (const float*)d_in[2];       // [4096]
    float* out = (float*)d_out;

    cudaFuncSetAttribute(bitlinear_gemm,
                         cudaFuncAttributeMaxDynamicSharedMemorySize, SMEM_TOTAL);

    convert_x_kernel<<<32768, 256>>>(x);          // 64M halfs / 8 per thread
    convert_w_kernel<<<8192, 256>>>(w);           // 16M halfs / 8 per thread
    align_nop_kernel<<<1, 32>>>();                // shift ncu -s 5 onto the GEMM
    bitlinear_gemm<<<dim3(N_TOTAL / BN, M_TOTAL / BM), THREADS, SMEM_TOTAL>>>(b, out);
}

// round 6
// speedup vs baseline: 1.0654x; 1.0654x over previous
#include <cuda_runtime.h>
#include <cuda_fp16.h>
#include <cstdint>

// Problem dims
#define M_TOTAL 16384   // 8 * 2048
#define N_TOTAL 4096
#define K_TOTAL 4096

// GEMM tiling: 128x128 CTA tile, 2 CTAs resident per SM
#define BM 128
#define BN 128
#define BK 64
#define NK (K_TOTAL / BK)        // 64 mainloop iterations
#define STAGES 3
#define THREADS 256              // 8 warps; 2x4 warp grid; warp tile 64x32

#define A_TILE_BYTES (BM * BK * 2)   // 16384
#define B_TILE_BYTES (BN * BK * 2)   // 16384
#define STAGE_BYTES (A_TILE_BYTES + B_TILE_BYTES)  // 32768
#define SMEM_BIAS   0                // 128 floats
#define SMEM_MBAR   512              // full[3] @512+8s, free[3] @536+8s
#define SMEM_STAGE0 1024
#define SMEM_TOTAL  (SMEM_STAGE0 + STAGES * STAGE_BYTES)  // 99328 (x2 CTAs <= 227KB)

// fp16 operand buffers (device globals: no runtime allocation allowed)
__device__ __align__(1024) __half g_xh[(size_t)M_TOTAL * K_TOTAL];
__device__ __align__(1024) __half g_wh[(size_t)N_TOTAL * K_TOTAL];

// ---------------------------------------------------------------- helpers

__device__ __forceinline__ uint32_t smem_u32(const void* p) {
    uint32_t a;
    asm("{ .reg .u64 t; cvta.to.shared.u64 t, %1; cvt.u32.u64 %0, t; }" : "=r"(a) : "l"(p));
    return a;
}

__device__ __forceinline__ uint32_t swz128(uint32_t off) {
    return off ^ ((off >> 3) & 0x70);
}

__device__ __forceinline__ float quantize_ste(float w) {
    float a = fminf(fabsf(w), 1.0f);
    float q = rintf(a * 255.0f) * (1.0f / 255.0f);
    return copysignf(q, w);
}

__device__ __forceinline__ uint32_t h2_as_u32(__half2 h) {
    return *reinterpret_cast<uint32_t*>(&h);
}

__device__ __forceinline__ void cp_async16(uint32_t dst, const void* src) {
    asm volatile("cp.async.cg.shared.global [%0], [%1], 16;" :: "r"(dst), "l"(src) : "memory");
}
__device__ __forceinline__ void cp_async_arrive(uint32_t mbar) {
    asm volatile("cp.async.mbarrier.arrive.noinc.shared.b64 [%0];" :: "r"(mbar) : "memory");
}

#define MBAR_INIT(a, n) \
    asm volatile("mbarrier.init.shared.b64 [%0], %1;" :: "r"(a), "r"((uint32_t)(n)) : "memory")
#define MBAR_ARRIVE(a) \
    asm volatile("mbarrier.arrive.shared.b64 _, [%0];" :: "r"(a) : "memory")

__device__ __forceinline__ void mbar_wait(uint32_t mbar, uint32_t parity) {
    uint32_t done;
    asm volatile(
        "{\n\t.reg .pred p;\n\t"
        "mbarrier.try_wait.parity.acquire.cta.shared::cta.b64 p, [%1], %2;\n\t"
        "selp.b32 %0, 1, 0, p;\n\t}"
        : "=r"(done) : "r"(mbar), "r"(parity) : "memory");
    if (!done) {
        asm volatile(
            "{\n\t.reg .pred P1;\n\t"
            "WL_%=:\n\t"
            "mbarrier.try_wait.parity.acquire.cta.shared::cta.b64 P1, [%0], %1, 0x989680;\n\t"
            "@P1 bra.uni WD_%=;\n\t"
            "bra.uni WL_%=;\n\t"
            "WD_%=:\n\t}"
            :: "r"(mbar), "r"(parity) : "memory");
    }
}

__device__ __forceinline__ void ldsm_x4(uint32_t* r, uint32_t addr) {
    asm volatile("ldmatrix.sync.aligned.m8n8.x4.shared.b16 {%0,%1,%2,%3}, [%4];"
                 : "=r"(r[0]), "=r"(r[1]), "=r"(r[2]), "=r"(r[3]) : "r"(addr));
}

__device__ __forceinline__ void mma_16816(float* c, const uint32_t* a, uint32_t b0, uint32_t b1) {
    asm volatile(
        "mma.sync.aligned.m16n8k16.row.col.f32.f16.f16.f32 "
        "{%0,%1,%2,%3}, {%4,%5,%6,%7}, {%8,%9}, {%0,%1,%2,%3};"
        : "+f"(c[0]), "+f"(c[1]), "+f"(c[2]), "+f"(c[3])
        : "r"(a[0]), "r"(a[1]), "r"(a[2]), "r"(a[3]), "r"(b0), "r"(b1));
}

// ---------------------------------------------------------------- pre-pass kernels

__global__ void convert_x_kernel(const float* __restrict__ x) {
    size_t e = ((size_t)blockIdx.x * blockDim.x + threadIdx.x) * 8;
    float4 a = *reinterpret_cast<const float4*>(x + e);
    float4 b = *reinterpret_cast<const float4*>(x + e + 4);
    uint4 o;
    o.x = h2_as_u32(__floats2half2_rn(a.x, a.y));
    o.y = h2_as_u32(__floats2half2_rn(a.z, a.w));
    o.z = h2_as_u32(__floats2half2_rn(b.x, b.y));
    o.w = h2_as_u32(__floats2half2_rn(b.z, b.w));
    *reinterpret_cast<uint4*>(g_xh + e) = o;
}

__global__ void convert_w_kernel(const float* __restrict__ w) {
    size_t e = ((size_t)blockIdx.x * blockDim.x + threadIdx.x) * 8;
    float4 a = *reinterpret_cast<const float4*>(w + e);
    float4 b = *reinterpret_cast<const float4*>(w + e + 4);
    uint4 o;
    o.x = h2_as_u32(__floats2half2_rn(quantize_ste(a.x), quantize_ste(a.y)));
    o.y = h2_as_u32(__floats2half2_rn(quantize_ste(a.z), quantize_ste(a.w)));
    o.z = h2_as_u32(__floats2half2_rn(quantize_ste(b.x), quantize_ste(b.y)));
    o.w = h2_as_u32(__floats2half2_rn(quantize_ste(b.z), quantize_ste(b.w)));
    *reinterpret_cast<uint4*>(g_wh + e) = o;
}

// no-op: shifts launch index so ncu (-s 5 -c 1) lands on the GEMM
__global__ void align_nop_kernel() {}

// ---------------------------------------------------------------- GEMM kernel
// CTA 128x128, BK=64, 256 threads, 8 warps (2 x 4), warp tile 64x32, 2 CTAs/SM.
// Per-stage mbarrier pipeline (no full-CTA rendezvous): warps slide freely.

__global__ void __launch_bounds__(THREADS, 2)
bitlinear_gemm(const float* __restrict__ bias, float* __restrict__ out) {
    extern __shared__ char smem[];
    uint32_t sb = smem_u32(smem);
    const int tid = threadIdx.x;
    const int wid = tid >> 5, lane = tid & 31;
    const int warp_m = wid >> 2, warp_n = wid & 3;     // 2 x 4 warps
    const uint32_t mt = blockIdx.y, nt = blockIdx.x;

    float* qb = reinterpret_cast<float*>(smem + SMEM_BIAS);
    if (tid < BN) qb[tid] = quantize_ste(bias[nt * BN + tid]);

    if (tid == 0) {
        #pragma unroll
        for (int s = 0; s < STAGES; s++) {
            MBAR_INIT(sb + SMEM_MBAR + s * 8, THREADS);       // full[s]
            MBAR_INIT(sb + SMEM_MBAR + 24 + s * 8, 8);        // free[s]
        }
    }
    __syncthreads();

    const __half* asrc = g_xh + (size_t)mt * BM * K_TOTAL;
    const __half* bsrc = g_wh + (size_t)nt * BN * K_TOTAL;

    // issue this thread's copies for data-iter p into stage p%3, arrive on full
    auto produce = [&](int p) {
        int s = p % STAGES;
        uint32_t abase = sb + SMEM_STAGE0 + s * STAGE_BYTES;
        uint32_t bbase = abase + A_TILE_BYTES;
        #pragma unroll
        for (int i = 0; i < 4; i++) {
            int c = tid + i * THREADS;            // 0..1023
            int row = c >> 3, kc = c & 7;
            cp_async16(abase + swz128(row * 128 + kc * 16),
                       asrc + (size_t)row * K_TOTAL + p * BK + kc * 8);
        }
        #pragma unroll
        for (int i = 0; i < 4; i++) {
            int c = tid + i * THREADS;
            int row = c >> 3, kc = c & 7;
            cp_async16(bbase + swz128(row * 128 + kc * 16),
                       bsrc + (size_t)row * K_TOTAL + p * BK + kc * 8);
        }
        cp_async_arrive(sb + SMEM_MBAR + s * 8);
    };

    produce(0);
    produce(1);

    // per-lane ldmatrix row mapping
    const int lrow = (lane & 7) + ((lane >> 3) & 1) * 8;
    const int lhi = lane >> 4;

    float acc[4][4][4];
    #pragma unroll
    for (int i = 0; i < 4; i++)
        #pragma unroll
        for (int j = 0; j < 4; j++)
            #pragma unroll
            for (int c = 0; c < 4; c++) acc[i][j][c] = 0.0f;

    // cursors (incremental: no div by 3)
    int cons_s = 0, cons_ph = 0;                 // consumer: stage, full-parity
    int prod_s = 2, prod_fw = 1;                 // producer: stage of p=kt+2, free-parity

    for (int kt = 0; kt < NK; kt++) {
        // ---- produce stage for kt+2 ----
        if (kt + 2 < NK) {
            if (kt > 0)   // first use of each stage needs no free-wait
                mbar_wait(sb + SMEM_MBAR + 24 + prod_s * 8, prod_fw);
            produce(kt + 2);
            if (++prod_s == STAGES) { prod_s = 0; prod_fw ^= 1; }
        }

        // ---- consume stage kt ----
        mbar_wait(sb + SMEM_MBAR + cons_s * 8, cons_ph);
        uint32_t abase = sb + SMEM_STAGE0 + cons_s * STAGE_BYTES;
        uint32_t bbase = abase + A_TILE_BYTES;

        #pragma unroll
        for (int kk = 0; kk < 4; kk++) {          // 4 k16-steps per BK=64
            uint32_t a[4][4], b[2][4];
            #pragma unroll
            for (int mi = 0; mi < 4; mi++) {
                int row = warp_m * 64 + mi * 16 + lrow;
                ldsm_x4(a[mi], abase + swz128(row * 128 + (kk * 2 + lhi) * 16));
            }
            #pragma unroll
            for (int ni = 0; ni < 2; ni++) {
                int row = warp_n * 32 + ni * 16 + lrow;
                ldsm_x4(b[ni], bbase + swz128(row * 128 + (kk * 2 + lhi) * 16));
            }
            #pragma unroll
            for (int mi = 0; mi < 4; mi++)
                #pragma unroll
                for (int j = 0; j < 4; j++) {
                    int ni = j >> 1, sel = j & 1;
                    mma_16816(acc[mi][j], a[mi], b[ni][0 + sel], b[ni][2 + sel]);
                }
        }

        // this warp is done reading stage cons_s
        if (lane == 0) MBAR_ARRIVE(sb + SMEM_MBAR + 24 + cons_s * 8);
        if (++cons_s == STAGES) { cons_s = 0; cons_ph ^= 1; }
    }

    __syncthreads();   // qb visibility for epilogue

    // ---- epilogue: registers -> gmem with quantized bias ----
    const int qrow = lane >> 2, qcol = (lane & 3) * 2;
    #pragma unroll
    for (int mi = 0; mi < 4; mi++) {
        #pragma unroll
        for (int j = 0; j < 4; j++) {
            int n_off = warp_n * 32 + j * 8 + qcol;
            float b0 = qb[n_off], b1 = qb[n_off + 1];
            size_t m0 = (size_t)mt * BM + warp_m * 64 + mi * 16 + qrow;
            float* p0 = out + m0 * N_TOTAL + nt * BN + n_off;
            float* p1 = p0 + 8 * N_TOTAL;
            float2 v0 = {acc[mi][j][0] + b0, acc[mi][j][1] + b1};
            float2 v1 = {acc[mi][j][2] + b0, acc[mi][j][3] + b1};
            *reinterpret_cast<float2*>(p0) = v0;
            *reinterpret_cast<float2*>(p1) = v1;
        }
    }
}

// ---------------------------------------------------------------- launch

extern "C" void kernel_launch(void* const* d_in, const int* in_sizes, int n_in,
                              void* d_out, int out_size) {
    const float* x = (const float*)d_in[0];       // [8, 2048, 4096]
    const float* w = (const float*)d_in[1];       // [4096, 4096]
    const float* b = (const float*)d_in[2];       // [4096]
    float* out = (float*)d_out;

    cudaFuncSetAttribute(bitlinear_gemm,
                         cudaFuncAttributeMaxDynamicSharedMemorySize, SMEM_TOTAL);

    convert_x_kernel<<<32768, 256>>>(x);          // 64M halfs / 8 per thread
    convert_w_kernel<<<8192, 256>>>(w);           // 16M halfs / 8 per thread
    align_nop_kernel<<<1, 32>>>();                // shift ncu -s 5 onto the GEMM
    bitlinear_gemm<<<dim3(N_TOTAL / BN, M_TOTAL / BM), THREADS, SMEM_TOTAL>>>(b, out);
}